// round 10
// baseline (speedup 1.0000x reference)
#include <cuda_runtime.h>
#include <cstdint>
#include <cmath>

#define RDIM 2000
#define TSTEPS 20000
#define NCTA 125
#define COLS 16          // columns per CTA (125*16 = 2000)
#define NTHR 256
#define RPAD 2048
#define SPIN_CAP (1u << 20)

// Plain state values, double-buffered by step parity. buf[t&1] holds h_t.
__device__ float g_hval[2][RPAD];
// Split epoch counters (one 16B line): sum == total publishes == 125*t.
__device__ __align__(16) unsigned g_cnt4[4];
// Watchdog: set when a spin exceeds SPIN_CAP; all spinners then bail.
__device__ int g_abort;
// State buffers for the stepped fallback path.
__device__ float g_hs[2][RPAD];

__global__ void esn_init_kernel() {
    int idx = blockIdx.x * blockDim.x + threadIdx.x;   // 16*256 = 4096
    if (idx < 2 * RPAD) {
        ((float*)g_hval)[idx] = 0.f;
        ((float*)g_hs)[idx]   = 0.f;
    }
    if (idx < 4) g_cnt4[idx] = 0u;
    if (idx == 4) g_abort = 0;
}

__device__ __forceinline__ unsigned long long addx2(unsigned long long a,
                                                    unsigned long long b) {
    unsigned long long r;
    asm("add.rn.f32x2 %0,%1,%2;" : "=l"(r) : "l"(a), "l"(b));
    return r;
}

#define LD_CNT4(r0, r1, r2, r3, p)                                          \
    asm volatile("ld.global.cg.v4.b32 {%0,%1,%2,%3},[%4];"                  \
                 : "=r"(r0), "=r"(r1), "=r"(r2), "=r"(r3) : "l"(p))

// ============================ FUSED (fast) PATH =============================
__global__ void __launch_bounds__(NTHR, 1) esn_kernel(
    const float* __restrict__ x,     // [T,1]
    const float* __restrict__ Win,   // [2,R]
    const float* __restrict__ W,     // [R,R] row-major
    const float* __restrict__ gain,  // [R]
    const float* __restrict__ bias,  // [R]
    float* __restrict__ out)         // [T,R]
{
    __shared__ __align__(16) float part[COLS][8];   // per-warp column partials

    const int tid  = threadIdx.x;
    const int lane = tid & 31;
    const int w    = tid >> 5;
    const int j0   = blockIdx.x * COLS;    // CTA's 16 columns
    const int ibase = tid * 8;             // 8 consecutive i's (== gather slice)

    // W slice: wreg[il*8+c] packs (W[i][j0+2c], W[i][j0+2c+1]), i = ibase+il.
    unsigned long long wreg[64];
#pragma unroll
    for (int il = 0; il < 8; il++) {
        int i = ibase + il;
#pragma unroll
        for (int c = 0; c < 8; c++) {
            float a = (i < RDIM) ? W[(size_t)i * RDIM + j0 + 2 * c]     : 0.f;
            float b = (i < RDIM) ? W[(size_t)i * RDIM + j0 + 2 * c + 1] : 0.f;
            asm("mov.b64 %0,{%1,%2};" : "=l"(wreg[il * 8 + c])
                : "r"(__float_as_uint(a)), "r"(__float_as_uint(b)));
        }
    }

    // Publisher constants (warp 0, lanes 0..15 own columns j0..j0+15).
    const int jw = j0 + (lane & 15);
    float wi0 = 0.f, wi1 = 0.f, gn = 1.f, bs = 0.f, h_prev = 0.f;
    if (w == 0 && lane < 16) {
        wi0 = Win[jw];
        wi1 = Win[RDIM + jw];
        gn  = gain[jw];
        bs  = bias[jw];
    }

    unsigned target = 0;       // sum-of-counters threshold for step t: 125*t
    bool dead = false;         // sticky after watchdog abort (tid 0 only)
    unsigned* const cp  = &g_cnt4[0];
    unsigned* const myc = &g_cnt4[blockIdx.x & 3];

    for (int t = 0; t < TSTEPS; t++) {
        float xt = __ldg(&x[t]);

        // ---- tid0: 2-deep pipelined relaxed poll + one acquire fence ----
        if (tid == 0 && target != 0u && !dead) {
            unsigned a0, a1, a2, a3, b0, b1, b2, b3, tries = 0;
            LD_CNT4(a0, a1, a2, a3, cp);
            for (;;) {
                LD_CNT4(b0, b1, b2, b3, cp);           // B in flight
                if (a0 + a1 + a2 + a3 >= target) break; // waits on A only
                LD_CNT4(a0, a1, a2, a3, cp);           // A in flight
                if (b0 + b1 + b2 + b3 >= target) break; // waits on B only
                if ((++tries & 127u) == 0u) {
                    int ab;
                    asm volatile("ld.global.cg.b32 %0,[%1];"
                                 : "=r"(ab) : "l"(&g_abort));
                    if (ab) { dead = true; break; }
                    if (tries > SPIN_CAP) {
                        asm volatile("st.global.cg.b32 [%0],%1;"
                                     :: "l"(&g_abort), "r"(1) : "memory");
                        dead = true; break;
                    }
                }
            }
            asm volatile("fence.acq_rel.gpu;" ::: "memory");
        }
        __syncthreads();   // BAR1: broadcasts tid0's acquire to the whole CTA

        // ---- Gather this thread's 8 h values straight into registers ----
        float h0, h1, h2, h3, h4, h5, h6, h7;
        {
            const float* gp = &g_hval[t & 1][ibase];
            asm volatile("ld.global.cg.v4.f32 {%0,%1,%2,%3},[%4];"
                         : "=f"(h0), "=f"(h1), "=f"(h2), "=f"(h3) : "l"(gp));
            asm volatile("ld.global.cg.v4.f32 {%0,%1,%2,%3},[%4];"
                         : "=f"(h4), "=f"(h5), "=f"(h6), "=f"(h7) : "l"(gp + 4));
        }
        float hv[8] = {h0, h1, h2, h3, h4, h5, h6, h7};

        // ---- Matvec: 8 i's x 16 cols per thread, packed f32x2 ----
        unsigned long long accp[8];
#pragma unroll
        for (int c = 0; c < 8; c++) accp[c] = 0ull;
#pragma unroll
        for (int il = 0; il < 8; il++) {
            unsigned long long hh;
            unsigned hu = __float_as_uint(hv[il]);
            asm("mov.b64 %0,{%1,%1};" : "=l"(hh) : "r"(hu));
#pragma unroll
            for (int c = 0; c < 8; c++)
                asm("fma.rn.f32x2 %0,%1,%2,%3;"
                    : "=l"(accp[c]) : "l"(hh), "l"(wreg[il * 8 + c]), "l"(accp[c]));
        }

        // ---- Reduce-scatter: lanes {2c,2c+1} end with column c's warp sum ----
        unsigned long long v[4];
        {
            bool hi = (lane & 16) != 0;
#pragma unroll
            for (int k = 0; k < 4; k++) {
                unsigned long long snd = hi ? accp[k] : accp[k + 4];
                unsigned long long rcv = __shfl_xor_sync(0xffffffffu, snd, 16);
                v[k] = addx2(hi ? accp[k + 4] : accp[k], rcv);
            }
        }
        unsigned long long u2[2];
        {
            bool hi = (lane & 8) != 0;
#pragma unroll
            for (int k = 0; k < 2; k++) {
                unsigned long long snd = hi ? v[k] : v[k + 2];
                unsigned long long rcv = __shfl_xor_sync(0xffffffffu, snd, 8);
                u2[k] = addx2(hi ? v[k + 2] : v[k], rcv);
            }
        }
        unsigned long long w64;
        {
            bool hi = (lane & 4) != 0;
            unsigned long long snd = hi ? u2[0] : u2[1];
            unsigned long long rcv = __shfl_xor_sync(0xffffffffu, snd, 4);
            w64 = addx2(hi ? u2[1] : u2[0], rcv);
        }
        float fsum;
        {
            float lo, hi_f;
            asm("mov.b64 {%0,%1},%2;" : "=f"(lo), "=f"(hi_f) : "l"(w64));
            bool hi = (lane & 2) != 0;
            float snd = hi ? lo : hi_f;
            float rcv = __shfl_xor_sync(0xffffffffu, snd, 2);
            fsum = (hi ? hi_f : lo) + rcv;
        }
        fsum += __shfl_xor_sync(0xffffffffu, fsum, 1);

        if ((lane & 1) == 0) part[lane >> 1][w] = fsum;
        __syncthreads();   // BAR2: part complete AND all gathers of step t done

        // ---- Warp 0: finalize, publish h FIRST, release-inc, then out ----
        if (w == 0) {
            float hn = 0.f;
            if (lane < 16) {
                float4 pa = *(const float4*)&part[lane][0];
                float4 pb = *(const float4*)&part[lane][4];
                float acc = ((pa.x + pa.y) + (pa.z + pa.w))
                          + ((pb.x + pb.y) + (pb.z + pb.w));
                float pre = fmaf(xt, wi0, wi1) + acc;   // u_t[j] + (hW)[j]
                hn = 0.7f * h_prev + 0.3f * tanhf(fmaf(gn, pre, bs));
                asm volatile("st.global.cg.b32 [%0],%1;"
                             :: "l"(&g_hval[(t + 1) & 1][jw]),
                                "r"(__float_as_uint(hn)) : "memory");
            }
            __syncwarp(0xffffffffu);
            if (lane == 0) {
                // Release-atomic: orders the 16 h stores (only) before the inc.
                asm volatile("red.release.gpu.global.add.u32 [%0],%1;"
                             :: "l"(myc), "r"(1u) : "memory");
            }
            // out[] store AFTER the release: off the publish critical path.
            if (lane < 16) {
                out[(size_t)t * RDIM + jw] = hn;
                h_prev = hn;
            }
        }
        target += 125u;
        // No trailing barrier: next step's poll (tid 0) gates everything, and
        // part[][] is rewritten only after the next BAR1.
    }
}

// ======================== STEPPED (fallback) PATH ===========================
__global__ void __launch_bounds__(NTHR) esn_step_kernel(
    const float* __restrict__ x, const float* __restrict__ Win,
    const float* __restrict__ W, const float* __restrict__ gain,
    const float* __restrict__ bias, float* __restrict__ out, int t)
{
    __shared__ float red[16][16];
    const int tid = threadIdx.x;
    const int c = tid & 15;
    const int g = tid >> 4;
    const int j = blockIdx.x * COLS + c;
    const float* hp = g_hs[t & 1];

    float acc = 0.f;
#pragma unroll 5
    for (int i = g; i < RDIM; i += 16)
        acc = fmaf(hp[i], W[(size_t)i * RDIM + j], acc);
    red[g][c] = acc;
    __syncthreads();

    if (tid < 16) {
        int jc = blockIdx.x * COLS + tid;
        float s = 0.f;
#pragma unroll
        for (int k = 0; k < 16; k++) s += red[k][tid];
        float xt   = __ldg(&x[t]);
        float pre  = fmaf(xt, Win[jc], Win[RDIM + jc]) + s;
        float hold = hp[jc];
        float hn   = 0.7f * hold + 0.3f * tanhf(fmaf(gain[jc], pre, bias[jc]));
        out[(size_t)t * RDIM + jc] = hn;
        g_hs[(t + 1) & 1][jc] = hn;
    }
}

extern "C" void kernel_launch(void* const* d_in, const int* in_sizes, int n_in,
                              void* d_out, int out_size) {
    const float* x    = (const float*)d_in[0];
    const float* Win  = (const float*)d_in[1];
    const float* W    = (const float*)d_in[2];
    const float* gain = (const float*)d_in[3];
    const float* bias = (const float*)d_in[4];
    float* out = (float*)d_out;
    (void)in_sizes; (void)n_in; (void)out_size;

    int dev = 0, sms = 0, maxb = 0;
    cudaGetDevice(&dev);
    cudaDeviceGetAttribute(&sms, cudaDevAttrMultiProcessorCount, dev);
    cudaOccupancyMaxActiveBlocksPerMultiprocessor(&maxb, esn_kernel, NTHR, 0);
    bool fused_ok = (maxb >= 1) && ((long long)sms * maxb >= NCTA) && (sms >= NCTA);

    esn_init_kernel<<<16, 256>>>();
    if (fused_ok) {
        esn_kernel<<<NCTA, NTHR>>>(x, Win, W, gain, bias, out);
    } else {
        for (int t = 0; t < TSTEPS; t++)
            esn_step_kernel<<<NCTA, NTHR>>>(x, Win, W, gain, bias, out, t);
    }
}